// round 14
// baseline (speedup 1.0000x reference)
#include <cuda_runtime.h>
#include <cuda_fp16.h>
#include <math.h>
#include <stdint.h>

// Problem constants
#define HDIM 768
#define DDIM 128
#define BATCH 64
#define SQ 128
#define SD 1024
#define NTOK_Q (BATCH * SQ)   // 8192
#define NTOK_D (BATCH * SD)   // 65536
#define NJCHUNK 8             // SD / 128
#define NBLK_Q (NTOK_Q / 128) // 64
#define NBLK_D (NTOK_D / 128) // 512

#define KC 32                 // K chunk (elements)
#define NSTAGE 3
#define LDH 40                // fp16 stage row stride (units): 80B = 5x16B odd
#define HSTG (128 * LDH * 2)  // 10240 B per fp16 stage
#define RING_OFF 1024

// proj layout (relative to ring = smem + RING_OFF):
//   W fp16 B-ring 3*HSTG @0, Abuf 2*HSTG @3*HSTG, RED @5*HSTG
#define ABUF_OFF  (3 * HSTG)               // 30720
#define PROJ_RED  (5 * HSTG)               // 51200
#define PROJ_SMEM (RING_OFF + PROJ_RED + 2048)   // 54272

// maxsim layout (R11 ring): A 3 stages @0, B 3 stages @3*HSTG, RED @6*HSTG
#define MS_BOFF  (3 * HSTG)
#define MS_RED   (6 * HSTG)
#define MS_SMEM  (RING_OFF + MS_RED + 2048)      // 64512

// Scratch (device globals: allocation-free per harness rules)
__device__ __half g_q_emb[NTOK_Q * DDIM];            // 2 MB
__device__ __half g_d_emb[(size_t)NTOK_D * DDIM];    // 16 MB
__device__ float  g_pmax[BATCH * NJCHUNK * SQ];      // 256 KB
__device__ __half g_w_h[DDIM * HDIM];                // 192 KB (fp16 W)

// ---------------------------------------------------------------------------
// helpers
// ---------------------------------------------------------------------------
__device__ __forceinline__ uint32_t s2u(const void* p) {
    return (uint32_t)__cvta_generic_to_shared(p);
}
__device__ __forceinline__ void cp16(uint32_t smem, const void* g) {
    asm volatile("cp.async.cg.shared.global [%0], [%1], 16;" :: "r"(smem), "l"(g));
}
#define CP_COMMIT() asm volatile("cp.async.commit_group;" ::: "memory")
#define CP_WAIT(n)  asm volatile("cp.async.wait_group %0;" :: "n"(n) : "memory")

#define MBARRIER_INIT(mb, n) \
    asm volatile("mbarrier.init.shared.b64 [%0], %1;" :: "r"((uint32_t)(mb)), "r"((uint32_t)(n)) : "memory")
#define MBARRIER_ARRIVE(mb) \
    asm volatile("mbarrier.arrive.shared.b64 _, [%0];" :: "r"((uint32_t)(mb)) : "memory")

__device__ __forceinline__ void mbar_wait(uint32_t mb, uint32_t parity) {
    uint32_t done;
    asm volatile("{\n\t.reg .pred p;\n\t"
                 "mbarrier.try_wait.parity.acquire.cta.shared::cta.b64 p, [%1], %2;\n\t"
                 "selp.b32 %0, 1, 0, p;\n\t}" : "=r"(done) : "r"(mb), "r"(parity) : "memory");
    while (!done) {
        asm volatile("{\n\t.reg .pred p;\n\t"
                     "mbarrier.try_wait.parity.acquire.cta.shared::cta.b64 p, [%1], %2, 0x989680;\n\t"
                     "selp.b32 %0, 1, 0, p;\n\t}" : "=r"(done) : "r"(mb), "r"(parity) : "memory");
    }
}

__device__ __forceinline__ void ldsm4(uint32_t& r0, uint32_t& r1, uint32_t& r2,
                                      uint32_t& r3, uint32_t addr) {
    asm volatile("ldmatrix.sync.aligned.m8n8.x4.shared.b16 {%0,%1,%2,%3}, [%4];"
                 : "=r"(r0), "=r"(r1), "=r"(r2), "=r"(r3) : "r"(addr));
}
__device__ __forceinline__ void mma16(float c[4], const uint32_t a[4], const uint32_t b[2]) {
    asm volatile("mma.sync.aligned.m16n8k16.row.col.f32.f16.f16.f32 "
                 "{%0,%1,%2,%3}, {%4,%5,%6,%7}, {%8,%9}, {%0,%1,%2,%3};"
                 : "+f"(c[0]), "+f"(c[1]), "+f"(c[2]), "+f"(c[3])
                 : "r"(a[0]), "r"(a[1]), "r"(a[2]), "r"(a[3]),
                   "r"(b[0]), "r"(b[1]));
}

// barriers: full[s] at sb+8+s*16, empty[s] at +8
#define MB_FULL(sb, s)  ((sb) + 8 + (uint32_t)(s) * 16)
#define MB_EMPTY(sb, s) ((sb) + 8 + (uint32_t)(s) * 16 + 8)

// fp16 fragment offsets (units of __half), [rows][k] storage, stride LDH.
__device__ __forceinline__ void frag_offsets16(int warp, int lane,
                                               uint32_t aOff[2], uint32_t bOff[4],
                                               int& warpM, int& warpN)
{
    warpM = (warp & 3) * 32;
    warpN = (warp >> 2) * 64;
    const int l7 = lane & 7, b3 = (lane >> 3) & 1, b4 = (lane >> 4) & 1;
#pragma unroll
    for (int i = 0; i < 2; i++)
        aOff[i] = (uint32_t)((warpM + i * 16 + l7 + b3 * 8) * LDH + b4 * 8);
#pragma unroll
    for (int jj = 0; jj < 4; jj++)
        bOff[jj] = (uint32_t)((warpN + jj * 16 + b4 * 8 + l7) * LDH + b3 * 8);
}

// Consume one KC=32 fp16 stage: 2 k16 steps, each 6 ldsm.x4 + 16 mma per warp.
__device__ __forceinline__ void consume_stage16(uint32_t aB, uint32_t bB,
                                                const uint32_t aOff[2],
                                                const uint32_t bOff[4],
                                                float acc[2][8][4])
{
#pragma unroll
    for (int ks = 0; ks < 2; ks++) {
        const uint32_t kb = ks * 32;   // 16 fp16 = 32 bytes
        uint32_t af[2][4], bf[8][2];
#pragma unroll
        for (int i = 0; i < 2; i++)
            ldsm4(af[i][0], af[i][1], af[i][2], af[i][3], aB + aOff[i] * 2 + kb);
#pragma unroll
        for (int jj = 0; jj < 4; jj++) {
            uint32_t r0, r1, r2, r3;
            ldsm4(r0, r1, r2, r3, bB + bOff[jj] * 2 + kb);
            bf[2 * jj][0] = r0;  bf[2 * jj][1] = r1;
            bf[2 * jj + 1][0] = r2;  bf[2 * jj + 1][1] = r3;
        }
#pragma unroll
        for (int i = 0; i < 2; i++)
#pragma unroll
            for (int j = 0; j < 8; j++) mma16(acc[i][j], af[i], bf[j]);
    }
}

// ---------------------------------------------------------------------------
// Kernel 0: convert W fp32 -> fp16 once (cp.async-able stream for producers).
// ---------------------------------------------------------------------------
__global__ __launch_bounds__(256) void cvt_w(const float* __restrict__ W)
{
    int i = blockIdx.x * 256 + threadIdx.x;      // float4 index
    float4 v = ((const float4*)W)[i];
    __half2 h0 = __floats2half2_rn(v.x, v.y);
    __half2 h1 = __floats2half2_rn(v.z, v.w);
    uint2 u;
    u.x = *(uint32_t*)&h0;  u.y = *(uint32_t*)&h1;
    *(uint2*)&g_w_h[(size_t)i * 4] = u;
}

// ---------------------------------------------------------------------------
// Kernel 1: projection + L2 normalize, fp16, warp-specialized.
// 320 threads: warps 8-9 = pure cp.async producers for W fp16 (3-stage ring).
// Warps 0-7 consumers: software-pipelined LDG of X fp32 (one chunk ahead),
// in-register cvt -> double-buffered fp16 Abuf -> ldmatrix + MMA.
// No raw-X smem staging: crossbar/stage 96KB -> 64KB.
// ---------------------------------------------------------------------------
__global__ __launch_bounds__(320, 2) void proj_tc(
    const float* __restrict__ Xq, const int* __restrict__ Mq,
    const float* __restrict__ Xd, const int* __restrict__ Md)
{
    extern __shared__ char smem[];
    const uint32_t sbase = s2u(smem);
    const uint32_t ring  = sbase + RING_OFF;
    const int tid  = threadIdx.x;
    const int lane = tid & 31;
    const int warp = tid >> 5;

    const bool isQ = blockIdx.x < NBLK_Q;
    const int  rb  = isQ ? blockIdx.x : (blockIdx.x - NBLK_Q);
    const int  row0 = rb * 128;
    const float* X = isQ ? Xq : Xd;
    const int*   M = isQ ? Mq : Md;
    __half*      E = isQ ? g_q_emb : g_d_emb;
    const float* gA = X + (size_t)row0 * HDIM;

    if (tid == 0) {
#pragma unroll
        for (int s = 0; s < NSTAGE; s++) {
            MBARRIER_INIT(MB_FULL(sbase, s), 64);
            MBARRIER_INIT(MB_EMPTY(sbase, s), 256);
        }
    }
    __syncthreads();
    const int NC = HDIM / KC;   // 24

    if (warp >= 8) {
        // ------------- PRODUCER (warps 8,9): W cp.async only -------------
        const int ptid = tid - 256;
        int ph = 1;
        for (int m = 0; m < NC; m++) {
            const int st = m % NSTAGE;
            mbar_wait(MB_EMPTY(sbase, st), (uint32_t)ph);
            const __half* w = g_w_h + m * KC;
            const uint32_t bdst = ring + (uint32_t)st * HSTG;
#pragma unroll
            for (int i = 0; i < 8; i++) {
                int idx = ptid + i * 64;
                int r = idx >> 2, c8 = (idx & 3) * 8;
                cp16(bdst + (uint32_t)(r * LDH + c8) * 2, w + (size_t)r * HDIM + c8);
            }
            CP_COMMIT();
            if (m >= 2) { CP_WAIT(2); MBARRIER_ARRIVE(MB_FULL(sbase, (m - 2) % NSTAGE)); }
            if (st == NSTAGE - 1) ph ^= 1;
        }
        CP_WAIT(1); MBARRIER_ARRIVE(MB_FULL(sbase, (NC - 2) % NSTAGE));
        CP_WAIT(0); MBARRIER_ARRIVE(MB_FULL(sbase, (NC - 1) % NSTAGE));
        return;
    }

    // ------------- CONSUMER (warps 0-7; 256 threads) -------------
    uint32_t aOff[2], bOff[4];
    int warpM, warpN;
    frag_offsets16(warp, lane, aOff, bOff, warpM, warpN);
    const int wn = warp >> 2;
    const int g = lane >> 2, tig = lane & 3;

    // X LDG mapping: pieces p = tid, tid+256 -> row r = tid&127,
    // float-offset (p>>7)*8 within the chunk.  8 floats per piece.
    const int xr  = tid & 127;
    const int xc0 = (tid >> 7) * 8;          // piece 0 float offset
    const float* xrow = gA + (size_t)xr * HDIM;

    float acc[2][8][4];
#pragma unroll
    for (int i = 0; i < 2; i++)
#pragma unroll
        for (int j = 0; j < 8; j++)
#pragma unroll
            for (int e = 0; e < 4; e++) acc[i][j][e] = 0.f;

    float4 xf[2][2];   // [piece][pair]
    // prologue: LDG chunk 0
#pragma unroll
    for (int i = 0; i < 2; i++) {
        const float* s = xrow + (xc0 + i * 16);
        xf[i][0] = *(const float4*)(s);
        xf[i][1] = *(const float4*)(s + 4);
    }

    {
        int st = 0, ph = 0;
        for (int k = 0; k < NC; k++) {
            // cvt chunk k (in regs) -> Abuf[k&1]
            char* ab = smem + RING_OFF + ABUF_OFF + (size_t)(k & 1) * HSTG;
#pragma unroll
            for (int i = 0; i < 2; i++) {
                __half2 h0 = __floats2half2_rn(xf[i][0].x, xf[i][0].y);
                __half2 h1 = __floats2half2_rn(xf[i][0].z, xf[i][0].w);
                __half2 h2 = __floats2half2_rn(xf[i][1].x, xf[i][1].y);
                __half2 h3 = __floats2half2_rn(xf[i][1].z, xf[i][1].w);
                uint4 u;
                u.x = *(uint32_t*)&h0;  u.y = *(uint32_t*)&h1;
                u.z = *(uint32_t*)&h2;  u.w = *(uint32_t*)&h3;
                *(uint4*)(ab + xr * (LDH * 2) + (xc0 + i * 16) * 2) = u;
            }
            // issue LDG for chunk k+1 (one stage of latency cover)
            if (k + 1 < NC) {
                const float* base = xrow + (k + 1) * KC;
#pragma unroll
                for (int i = 0; i < 2; i++) {
                    const float* s = base + (xc0 + i * 16);
                    xf[i][0] = *(const float4*)(s);
                    xf[i][1] = *(const float4*)(s + 4);
                }
            }
            asm volatile("bar.sync 1, 256;" ::: "memory");   // Abuf visible
            mbar_wait(MB_FULL(sbase, st), (uint32_t)ph);
            consume_stage16(ring + ABUF_OFF + (uint32_t)(k & 1) * HSTG,
                            ring + (uint32_t)st * HSTG,
                            aOff, bOff, acc);
            MBARRIER_ARRIVE(MB_EMPTY(sbase, st));
            if (++st == NSTAGE) { st = 0; ph ^= 1; }
        }
    }
    asm volatile("bar.sync 1, 256;" ::: "memory");

    // ---- fused L2 normalize (mask folded into scale) ----
    float* ssb = (float*)(smem + RING_OFF + PROJ_RED);   // [2][128]
#pragma unroll
    for (int i = 0; i < 2; i++) {
        float sl = 0.f, sh = 0.f;
#pragma unroll
        for (int j = 0; j < 8; j++) {
            sl += acc[i][j][0] * acc[i][j][0] + acc[i][j][1] * acc[i][j][1];
            sh += acc[i][j][2] * acc[i][j][2] + acc[i][j][3] * acc[i][j][3];
        }
        sl += __shfl_xor_sync(0xffffffffu, sl, 1);
        sl += __shfl_xor_sync(0xffffffffu, sl, 2);
        sh += __shfl_xor_sync(0xffffffffu, sh, 1);
        sh += __shfl_xor_sync(0xffffffffu, sh, 2);
        if (tig == 0) {
            ssb[wn * 128 + warpM + i * 16 + g]     = sl;
            ssb[wn * 128 + warpM + i * 16 + 8 + g] = sh;
        }
    }
    asm volatile("bar.sync 1, 256;" ::: "memory");
#pragma unroll
    for (int i = 0; i < 2; i++) {
        const int rl = warpM + i * 16 + g;
        const int rh = rl + 8;
        const float scl = (float)M[row0 + rl] / fmaxf(sqrtf(ssb[rl] + ssb[128 + rl]), 1e-12f);
        const float sch = (float)M[row0 + rh] / fmaxf(sqrtf(ssb[rh] + ssb[128 + rh]), 1e-12f);
#pragma unroll
        for (int j = 0; j < 8; j++) {
            const int col = warpN + j * 8 + tig * 2;
            __half2 v;
            v = __floats2half2_rn(acc[i][j][0] * scl, acc[i][j][1] * scl);
            *(__half2*)&E[(size_t)(row0 + rl) * DDIM + col] = v;
            v = __floats2half2_rn(acc[i][j][2] * sch, acc[i][j][3] * sch);
            *(__half2*)&E[(size_t)(row0 + rh) * DDIM + col] = v;
        }
    }
}

// ---------------------------------------------------------------------------
// Kernel 2: per-batch similarity + partial max (fp16, 3-stage ring — R11).
// Block (b, jc): [128 q x 128 docs], K = 128 dims (4 chunks of 32).
// ---------------------------------------------------------------------------
__global__ __launch_bounds__(256, 2) void maxsim_tc()
{
    extern __shared__ char smem[];
    const uint32_t sbase = s2u(smem);
    const uint32_t ring  = sbase + RING_OFF;
    const int tid  = threadIdx.x;
    const int lane = tid & 31;
    const int warp = tid >> 5;
    const int b  = blockIdx.x;
    const int jc = blockIdx.y;

    const __half* q = g_q_emb + (size_t)b * SQ * DDIM;
    const __half* d = g_d_emb + ((size_t)b * SD + (size_t)jc * 128) * DDIM;

    uint32_t aOff[2], bOff[4];
    int warpM, warpN;
    frag_offsets16(warp, lane, aOff, bOff, warpM, warpN);
    const int wn = warp >> 2;
    const int g = lane >> 2, tig = lane & 3;

    float acc[2][8][4];
#pragma unroll
    for (int i = 0; i < 2; i++)
#pragma unroll
        for (int j = 0; j < 8; j++)
#pragma unroll
            for (int e = 0; e < 4; e++) acc[i][j][e] = 0.f;

    auto load_stage = [&](int st, int m) {
        const __half* a  = q + m * KC;
        const __half* dd = d + m * KC;
        const uint32_t smA = ring + (uint32_t)st * HSTG;
        const uint32_t smB = ring + MS_BOFF + (uint32_t)st * HSTG;
#pragma unroll
        for (int i = 0; i < 2; i++) {
            int idx = tid + i * 256;         // [0,512)
            int r = idx >> 2, c8 = (idx & 3) * 8;
            uint32_t off = (uint32_t)(r * LDH + c8) * 2;
            cp16(smA + off, a + (size_t)r * DDIM + c8);
            cp16(smB + off, dd + (size_t)r * DDIM + c8);
        }
    };

    load_stage(0, 0); CP_COMMIT();
    load_stage(1, 1); CP_COMMIT();

    const int NC = DDIM / KC;   // 4
    int st = 0, stn = 2;
    for (int k = 0; k < NC; k++) {
        CP_WAIT(1);
        __syncthreads();
        const int m = k + 2;
        if (m < NC) { load_stage(stn, m); CP_COMMIT(); }
        consume_stage16(ring + (uint32_t)st * HSTG,
                        ring + MS_BOFF + (uint32_t)st * HSTG,
                        aOff, bOff, acc);
        st = (st + 1 == NSTAGE) ? 0 : st + 1;
        stn = (stn + 1 == NSTAGE) ? 0 : stn + 1;
    }
    __syncthreads();

    // ---- row max over this 128-doc chunk ----
    float* mxb = (float*)(smem + RING_OFF + MS_RED);   // [2][128]
#pragma unroll
    for (int i = 0; i < 2; i++) {
        float ml = acc[i][0][0], mh = acc[i][0][2];
#pragma unroll
        for (int j = 0; j < 8; j++) {
            ml = fmaxf(ml, fmaxf(acc[i][j][0], acc[i][j][1]));
            mh = fmaxf(mh, fmaxf(acc[i][j][2], acc[i][j][3]));
        }
        ml = fmaxf(ml, __shfl_xor_sync(0xffffffffu, ml, 1));
        ml = fmaxf(ml, __shfl_xor_sync(0xffffffffu, ml, 2));
        mh = fmaxf(mh, __shfl_xor_sync(0xffffffffu, mh, 1));
        mh = fmaxf(mh, __shfl_xor_sync(0xffffffffu, mh, 2));
        if (tig == 0) {
            mxb[wn * 128 + warpM + i * 16 + g]     = ml;
            mxb[wn * 128 + warpM + i * 16 + 8 + g] = mh;
        }
    }
    __syncthreads();
    if (tid < 128)
        g_pmax[((size_t)b * NJCHUNK + jc) * SQ + tid] =
            fmaxf(mxb[tid], mxb[128 + tid]);
}

// ---------------------------------------------------------------------------
// Kernel 3: finalize. out[b] = sum_i max_jc pmax[b, jc, i]
// ---------------------------------------------------------------------------
__global__ __launch_bounds__(128) void finalize_kernel(float* __restrict__ out)
{
    const int b = blockIdx.x;
    const int i = threadIdx.x;
    float m = g_pmax[((size_t)b * NJCHUNK + 0) * SQ + i];
#pragma unroll
    for (int jc = 1; jc < NJCHUNK; jc++)
        m = fmaxf(m, g_pmax[((size_t)b * NJCHUNK + jc) * SQ + i]);
#pragma unroll
    for (int o = 16; o > 0; o >>= 1)
        m += __shfl_xor_sync(0xffffffffu, m, o, 32);
    __shared__ float s[4];
    if ((i & 31) == 0) s[i >> 5] = m;
    __syncthreads();
    if (i == 0) out[b] = s[0] + s[1] + s[2] + s[3];
}

// ---------------------------------------------------------------------------
extern "C" void kernel_launch(void* const* d_in, const int* in_sizes, int n_in,
                              void* d_out, int out_size)
{
    const float* qh = (const float*)d_in[0];   // [64,128,768]
    const int*   qm = (const int*)  d_in[1];   // [64,128]
    const float* dh = (const float*)d_in[2];   // [64,1024,768]
    const int*   dm = (const int*)  d_in[3];   // [64,1024]
    const float* W  = (const float*)d_in[4];   // [128,768]
    float* out = (float*)d_out;                // [64]

    cudaFuncSetAttribute(proj_tc,   cudaFuncAttributeMaxDynamicSharedMemorySize, PROJ_SMEM);
    cudaFuncSetAttribute(maxsim_tc, cudaFuncAttributeMaxDynamicSharedMemorySize, MS_SMEM);

    cvt_w<<<(DDIM * HDIM / 4) / 256, 256>>>(W);
    proj_tc<<<NBLK_Q + NBLK_D, 320, PROJ_SMEM>>>(qh, qm, dh, dm);
    maxsim_tc<<<dim3(BATCH, NJCHUNK), 256, MS_SMEM>>>();
    finalize_kernel<<<BATCH, 128>>>(out);
}

// round 15
// speedup vs baseline: 1.9519x; 1.9519x over previous
#include <cuda_runtime.h>
#include <cuda_fp16.h>
#include <math.h>
#include <stdint.h>

// Problem constants
#define HDIM 768
#define DDIM 128
#define BATCH 64
#define SQ 128
#define SD 1024
#define NTOK_Q (BATCH * SQ)   // 8192
#define NTOK_D (BATCH * SD)   // 65536
#define NJCHUNK 8             // SD / 128
#define NBLK_Q (NTOK_Q / 128) // 64
#define NBLK_D (NTOK_D / 128) // 512

#define KC 32                 // K chunk (elements)
#define NSTAGE 3
#define LDH 40                // fp16 stage row stride (units): 80B = 5x16B odd
#define HSTG (128 * LDH * 2)  // 10240 B per fp16 stage
#define RAWLD 36              // raw fp32 row stride (floats): 144B = 9x16B odd
#define RAWSTG (128 * RAWLD * 4)   // 18432 B
#define RING_OFF 1024

// proj layout (relative to ring = smem + RING_OFF):
//   raw X ring 3*RAWSTG @0, W fp16 ring 3*HSTG @55296, Abuf 2*HSTG @86016, RED @106496
#define PBRING_OFF (3 * RAWSTG)            // 55296
#define ABUF_OFF  (PBRING_OFF + 3 * HSTG)  // 86016
#define PROJ_RED  (ABUF_OFF + 2 * HSTG)    // 106496
#define PROJ_SMEM (RING_OFF + PROJ_RED + 2048)   // 109568

// maxsim layout: A 3 stages @0, B 3 stages @3*HSTG, RED @6*HSTG
#define MS_BOFF  (3 * HSTG)
#define MS_RED   (6 * HSTG)
#define MS_SMEM  (RING_OFF + MS_RED + 2048)      // 64512

// Scratch (device globals: allocation-free per harness rules)
__device__ __half g_q_emb[NTOK_Q * DDIM];            // 2 MB
__device__ __half g_d_emb[(size_t)NTOK_D * DDIM];    // 16 MB
__device__ float  g_pmax[BATCH * NJCHUNK * SQ];      // 256 KB
__device__ __half g_w_h[DDIM * HDIM];                // 192 KB (fp16 W)

// ---------------------------------------------------------------------------
// helpers
// ---------------------------------------------------------------------------
__device__ __forceinline__ uint32_t s2u(const void* p) {
    return (uint32_t)__cvta_generic_to_shared(p);
}
__device__ __forceinline__ void cp16(uint32_t smem, const void* g) {
    asm volatile("cp.async.cg.shared.global [%0], [%1], 16;" :: "r"(smem), "l"(g));
}
#define CP_COMMIT() asm volatile("cp.async.commit_group;" ::: "memory")
#define CP_WAIT(n)  asm volatile("cp.async.wait_group %0;" :: "n"(n) : "memory")

#define MBARRIER_INIT(mb, n) \
    asm volatile("mbarrier.init.shared.b64 [%0], %1;" :: "r"((uint32_t)(mb)), "r"((uint32_t)(n)) : "memory")
#define MBARRIER_ARRIVE(mb) \
    asm volatile("mbarrier.arrive.shared.b64 _, [%0];" :: "r"((uint32_t)(mb)) : "memory")

__device__ __forceinline__ void mbar_wait(uint32_t mb, uint32_t parity) {
    uint32_t done;
    asm volatile("{\n\t.reg .pred p;\n\t"
                 "mbarrier.try_wait.parity.acquire.cta.shared::cta.b64 p, [%1], %2;\n\t"
                 "selp.b32 %0, 1, 0, p;\n\t}" : "=r"(done) : "r"(mb), "r"(parity) : "memory");
    while (!done) {
        asm volatile("{\n\t.reg .pred p;\n\t"
                     "mbarrier.try_wait.parity.acquire.cta.shared::cta.b64 p, [%1], %2, 0x989680;\n\t"
                     "selp.b32 %0, 1, 0, p;\n\t}" : "=r"(done) : "r"(mb), "r"(parity) : "memory");
    }
}

__device__ __forceinline__ void ldsm4(uint32_t& r0, uint32_t& r1, uint32_t& r2,
                                      uint32_t& r3, uint32_t addr) {
    asm volatile("ldmatrix.sync.aligned.m8n8.x4.shared.b16 {%0,%1,%2,%3}, [%4];"
                 : "=r"(r0), "=r"(r1), "=r"(r2), "=r"(r3) : "r"(addr));
}
__device__ __forceinline__ void mma16(float c[4], const uint32_t a[4], const uint32_t b[2]) {
    asm volatile("mma.sync.aligned.m16n8k16.row.col.f32.f16.f16.f32 "
                 "{%0,%1,%2,%3}, {%4,%5,%6,%7}, {%8,%9}, {%0,%1,%2,%3};"
                 : "+f"(c[0]), "+f"(c[1]), "+f"(c[2]), "+f"(c[3])
                 : "r"(a[0]), "r"(a[1]), "r"(a[2]), "r"(a[3]),
                   "r"(b[0]), "r"(b[1]));
}

// barriers: full[s] @ sb+8+s*16, rawempty[s] @ +8, wempty[s] @ sb+56+s*16
#define MB_FULL(sb, s)  ((sb) + 8 + (uint32_t)(s) * 16)
#define MB_RAWE(sb, s)  ((sb) + 8 + (uint32_t)(s) * 16 + 8)
#define MB_WE(sb, s)    ((sb) + 56 + (uint32_t)(s) * 16)

// fp16 fragment offsets (units of __half), [rows][k] storage, stride LDH.
__device__ __forceinline__ void frag_offsets16(int warp, int lane,
                                               uint32_t aOff[2], uint32_t bOff[4],
                                               int& warpM, int& warpN)
{
    warpM = (warp & 3) * 32;
    warpN = (warp >> 2) * 64;
    const int l7 = lane & 7, b3 = (lane >> 3) & 1, b4 = (lane >> 4) & 1;
#pragma unroll
    for (int i = 0; i < 2; i++)
        aOff[i] = (uint32_t)((warpM + i * 16 + l7 + b3 * 8) * LDH + b4 * 8);
#pragma unroll
    for (int jj = 0; jj < 4; jj++)
        bOff[jj] = (uint32_t)((warpN + jj * 16 + b4 * 8 + l7) * LDH + b3 * 8);
}

// Consume one KC=32 fp16 stage: 2 k16 steps, each 6 ldsm.x4 + 16 mma per warp.
__device__ __forceinline__ void consume_stage16(uint32_t aB, uint32_t bB,
                                                const uint32_t aOff[2],
                                                const uint32_t bOff[4],
                                                float acc[2][8][4])
{
#pragma unroll
    for (int ks = 0; ks < 2; ks++) {
        const uint32_t kb = ks * 32;   // 16 fp16 = 32 bytes
        uint32_t af[2][4], bf[8][2];
#pragma unroll
        for (int i = 0; i < 2; i++)
            ldsm4(af[i][0], af[i][1], af[i][2], af[i][3], aB + aOff[i] * 2 + kb);
#pragma unroll
        for (int jj = 0; jj < 4; jj++) {
            uint32_t r0, r1, r2, r3;
            ldsm4(r0, r1, r2, r3, bB + bOff[jj] * 2 + kb);
            bf[2 * jj][0] = r0;  bf[2 * jj][1] = r1;
            bf[2 * jj + 1][0] = r2;  bf[2 * jj + 1][1] = r3;
        }
#pragma unroll
        for (int i = 0; i < 2; i++)
#pragma unroll
            for (int j = 0; j < 8; j++) mma16(acc[i][j], af[i], bf[j]);
    }
}

// ---------------------------------------------------------------------------
// Kernel 0: convert W fp32 -> fp16 once (cp.async-able stream for producers).
// ---------------------------------------------------------------------------
__global__ __launch_bounds__(256) void cvt_w(const float* __restrict__ W)
{
    int i = blockIdx.x * 256 + threadIdx.x;      // float4 index
    float4 v = ((const float4*)W)[i];
    __half2 h0 = __floats2half2_rn(v.x, v.y);
    __half2 h1 = __floats2half2_rn(v.z, v.w);
    uint2 u;
    u.x = *(uint32_t*)&h0;  u.y = *(uint32_t*)&h1;
    *(uint2*)&g_w_h[(size_t)i * 4] = u;
}

// ---------------------------------------------------------------------------
// Kernel 1: projection + L2 normalize, fp16, warp-specialized (R11 + split
// empty barriers).  320 threads: warps 8-9 = pure cp.async producers (X fp32
// -> raw ring, W fp16 -> B ring, 3-stage).  Warps 0-7 = consumers:
// distributed fp32->fp16 convert (raw -> double-buffered Abuf), ldmatrix+MMA.
// Consumers release the raw-X ring right after the cvt (rawempty) and the W
// ring after the MMA (wempty), giving producers earlier X-stream lead.
// ---------------------------------------------------------------------------
__global__ __launch_bounds__(320, 2) void proj_tc(
    const float* __restrict__ Xq, const int* __restrict__ Mq,
    const float* __restrict__ Xd, const int* __restrict__ Md)
{
    extern __shared__ char smem[];
    const uint32_t sbase = s2u(smem);
    const uint32_t ring  = sbase + RING_OFF;
    const int tid  = threadIdx.x;
    const int lane = tid & 31;
    const int warp = tid >> 5;

    const bool isQ = blockIdx.x < NBLK_Q;
    const int  rb  = isQ ? blockIdx.x : (blockIdx.x - NBLK_Q);
    const int  row0 = rb * 128;
    const float* X = isQ ? Xq : Xd;
    const int*   M = isQ ? Mq : Md;
    __half*      E = isQ ? g_q_emb : g_d_emb;
    const float* gA = X + (size_t)row0 * HDIM;

    if (tid == 0) {
#pragma unroll
        for (int s = 0; s < NSTAGE; s++) {
            MBARRIER_INIT(MB_FULL(sbase, s), 64);
            MBARRIER_INIT(MB_RAWE(sbase, s), 256);
            MBARRIER_INIT(MB_WE(sbase, s), 256);
        }
    }
    __syncthreads();
    const int NC = HDIM / KC;   // 24

    if (warp >= 8) {
        // ------------- PRODUCER (warps 8,9): cp.async only -------------
        const int ptid = tid - 256;
        int ph = 1;
        for (int m = 0; m < NC; m++) {
            const int st = m % NSTAGE;
            // raw-X of stage st is free as soon as consumers finished its cvt
            mbar_wait(MB_RAWE(sbase, st), (uint32_t)ph);
            const float* a = gA + m * KC;
            const uint32_t rawdst = ring + (uint32_t)st * RAWSTG;
#pragma unroll
            for (int i = 0; i < 16; i++) {
                int idx = ptid + i * 64;
                int r = idx >> 3, c = (idx & 7) * 4;
                cp16(rawdst + (uint32_t)(r * RAWLD + c) * 4, a + (size_t)r * HDIM + c);
            }
            // W ring of stage st frees only after the MMA consumed it
            mbar_wait(MB_WE(sbase, st), (uint32_t)ph);
            const __half* w = g_w_h + m * KC;
            const uint32_t bdst = ring + PBRING_OFF + (uint32_t)st * HSTG;
#pragma unroll
            for (int i = 0; i < 8; i++) {
                int idx = ptid + i * 64;
                int r = idx >> 2, c8 = (idx & 3) * 8;
                cp16(bdst + (uint32_t)(r * LDH + c8) * 2, w + (size_t)r * HDIM + c8);
            }
            CP_COMMIT();
            if (m >= 2) { CP_WAIT(2); MBARRIER_ARRIVE(MB_FULL(sbase, (m - 2) % NSTAGE)); }
            if (st == NSTAGE - 1) ph ^= 1;
        }
        CP_WAIT(1); MBARRIER_ARRIVE(MB_FULL(sbase, (NC - 2) % NSTAGE));
        CP_WAIT(0); MBARRIER_ARRIVE(MB_FULL(sbase, (NC - 1) % NSTAGE));
        return;
    }

    // ------------- CONSUMER (warps 0-7; 256 threads) -------------
    uint32_t aOff[2], bOff[4];
    int warpM, warpN;
    frag_offsets16(warp, lane, aOff, bOff, warpM, warpN);
    const int wn = warp >> 2;
    const int g = lane >> 2, tig = lane & 3;

    float acc[2][8][4];
#pragma unroll
    for (int i = 0; i < 2; i++)
#pragma unroll
        for (int j = 0; j < 8; j++)
#pragma unroll
            for (int e = 0; e < 4; e++) acc[i][j][e] = 0.f;

    {
        int st = 0, ph = 0;
        for (int k = 0; k < NC; k++) {
            mbar_wait(MB_FULL(sbase, st), (uint32_t)ph);
            // distributed cvt: raw[st] fp32 -> Abuf[k&1] fp16
            const char* rawb = smem + RING_OFF + (size_t)st * RAWSTG;
            char* ab = smem + RING_OFF + ABUF_OFF + (size_t)(k & 1) * HSTG;
#pragma unroll
            for (int i = 0; i < 2; i++) {
                int p = tid + i * 256;
                int r = p & 127, cp = p >> 7;
                const char* src = rawb + r * (RAWLD * 4) + cp * 32;
                float4 f0 = *(const float4*)(src);
                float4 f1 = *(const float4*)(src + 16);
                __half2 h0 = __floats2half2_rn(f0.x, f0.y);
                __half2 h1 = __floats2half2_rn(f0.z, f0.w);
                __half2 h2 = __floats2half2_rn(f1.x, f1.y);
                __half2 h3 = __floats2half2_rn(f1.z, f1.w);
                uint4 u;
                u.x = *(uint32_t*)&h0;  u.y = *(uint32_t*)&h1;
                u.z = *(uint32_t*)&h2;  u.w = *(uint32_t*)&h3;
                *(uint4*)(ab + r * (LDH * 2) + cp * 16) = u;
            }
            MBARRIER_ARRIVE(MB_RAWE(sbase, st));   // raw[st] reads done (this thread)
            asm volatile("bar.sync 1, 256;" ::: "memory");   // Abuf visible
            consume_stage16(ring + ABUF_OFF + (uint32_t)(k & 1) * HSTG,
                            ring + PBRING_OFF + (uint32_t)st * HSTG,
                            aOff, bOff, acc);
            MBARRIER_ARRIVE(MB_WE(sbase, st));     // W ring[st] reads done
            if (++st == NSTAGE) { st = 0; ph ^= 1; }
        }
    }
    asm volatile("bar.sync 1, 256;" ::: "memory");

    // ---- fused L2 normalize (mask folded into scale) ----
    float* ssb = (float*)(smem + RING_OFF + PROJ_RED);   // [2][128]
#pragma unroll
    for (int i = 0; i < 2; i++) {
        float sl = 0.f, sh = 0.f;
#pragma unroll
        for (int j = 0; j < 8; j++) {
            sl += acc[i][j][0] * acc[i][j][0] + acc[i][j][1] * acc[i][j][1];
            sh += acc[i][j][2] * acc[i][j][2] + acc[i][j][3] * acc[i][j][3];
        }
        sl += __shfl_xor_sync(0xffffffffu, sl, 1);
        sl += __shfl_xor_sync(0xffffffffu, sl, 2);
        sh += __shfl_xor_sync(0xffffffffu, sh, 1);
        sh += __shfl_xor_sync(0xffffffffu, sh, 2);
        if (tig == 0) {
            ssb[wn * 128 + warpM + i * 16 + g]     = sl;
            ssb[wn * 128 + warpM + i * 16 + 8 + g] = sh;
        }
    }
    asm volatile("bar.sync 1, 256;" ::: "memory");
#pragma unroll
    for (int i = 0; i < 2; i++) {
        const int rl = warpM + i * 16 + g;
        const int rh = rl + 8;
        const float scl = (float)M[row0 + rl] / fmaxf(sqrtf(ssb[rl] + ssb[128 + rl]), 1e-12f);
        const float sch = (float)M[row0 + rh] / fmaxf(sqrtf(ssb[rh] + ssb[128 + rh]), 1e-12f);
#pragma unroll
        for (int j = 0; j < 8; j++) {
            const int col = warpN + j * 8 + tig * 2;
            __half2 v;
            v = __floats2half2_rn(acc[i][j][0] * scl, acc[i][j][1] * scl);
            *(__half2*)&E[(size_t)(row0 + rl) * DDIM + col] = v;
            v = __floats2half2_rn(acc[i][j][2] * sch, acc[i][j][3] * sch);
            *(__half2*)&E[(size_t)(row0 + rh) * DDIM + col] = v;
        }
    }
}

// ---------------------------------------------------------------------------
// Kernel 2: per-batch similarity + partial max (fp16, 3-stage ring — R11).
// Block (b, jc): [128 q x 128 docs], K = 128 dims (4 chunks of 32).
// ---------------------------------------------------------------------------
__global__ __launch_bounds__(256, 2) void maxsim_tc()
{
    extern __shared__ char smem[];
    const uint32_t sbase = s2u(smem);
    const uint32_t ring  = sbase + RING_OFF;
    const int tid  = threadIdx.x;
    const int lane = tid & 31;
    const int warp = tid >> 5;
    const int b  = blockIdx.x;
    const int jc = blockIdx.y;

    const __half* q = g_q_emb + (size_t)b * SQ * DDIM;
    const __half* d = g_d_emb + ((size_t)b * SD + (size_t)jc * 128) * DDIM;

    uint32_t aOff[2], bOff[4];
    int warpM, warpN;
    frag_offsets16(warp, lane, aOff, bOff, warpM, warpN);
    const int wn = warp >> 2;
    const int g = lane >> 2, tig = lane & 3;

    float acc[2][8][4];
#pragma unroll
    for (int i = 0; i < 2; i++)
#pragma unroll
        for (int j = 0; j < 8; j++)
#pragma unroll
            for (int e = 0; e < 4; e++) acc[i][j][e] = 0.f;

    auto load_stage = [&](int st, int m) {
        const __half* a  = q + m * KC;
        const __half* dd = d + m * KC;
        const uint32_t smA = ring + (uint32_t)st * HSTG;
        const uint32_t smB = ring + MS_BOFF + (uint32_t)st * HSTG;
#pragma unroll
        for (int i = 0; i < 2; i++) {
            int idx = tid + i * 256;         // [0,512)
            int r = idx >> 2, c8 = (idx & 3) * 8;
            uint32_t off = (uint32_t)(r * LDH + c8) * 2;
            cp16(smA + off, a + (size_t)r * DDIM + c8);
            cp16(smB + off, dd + (size_t)r * DDIM + c8);
        }
    };

    load_stage(0, 0); CP_COMMIT();
    load_stage(1, 1); CP_COMMIT();

    const int NC = DDIM / KC;   // 4
    int st = 0, stn = 2;
    for (int k = 0; k < NC; k++) {
        CP_WAIT(1);
        __syncthreads();
        const int m = k + 2;
        if (m < NC) { load_stage(stn, m); CP_COMMIT(); }
        consume_stage16(ring + (uint32_t)st * HSTG,
                        ring + MS_BOFF + (uint32_t)st * HSTG,
                        aOff, bOff, acc);
        st = (st + 1 == NSTAGE) ? 0 : st + 1;
        stn = (stn + 1 == NSTAGE) ? 0 : stn + 1;
    }
    __syncthreads();

    // ---- row max over this 128-doc chunk ----
    float* mxb = (float*)(smem + RING_OFF + MS_RED);   // [2][128]
#pragma unroll
    for (int i = 0; i < 2; i++) {
        float ml = acc[i][0][0], mh = acc[i][0][2];
#pragma unroll
        for (int j = 0; j < 8; j++) {
            ml = fmaxf(ml, fmaxf(acc[i][j][0], acc[i][j][1]));
            mh = fmaxf(mh, fmaxf(acc[i][j][2], acc[i][j][3]));
        }
        ml = fmaxf(ml, __shfl_xor_sync(0xffffffffu, ml, 1));
        ml = fmaxf(ml, __shfl_xor_sync(0xffffffffu, ml, 2));
        mh = fmaxf(mh, __shfl_xor_sync(0xffffffffu, mh, 1));
        mh = fmaxf(mh, __shfl_xor_sync(0xffffffffu, mh, 2));
        if (tig == 0) {
            mxb[wn * 128 + warpM + i * 16 + g]     = ml;
            mxb[wn * 128 + warpM + i * 16 + 8 + g] = mh;
        }
    }
    __syncthreads();
    if (tid < 128)
        g_pmax[((size_t)b * NJCHUNK + jc) * SQ + tid] =
            fmaxf(mxb[tid], mxb[128 + tid]);
}

// ---------------------------------------------------------------------------
// Kernel 3: finalize. out[b] = sum_i max_jc pmax[b, jc, i]
// ---------------------------------------------------------------------------
__global__ __launch_bounds__(128) void finalize_kernel(float* __restrict__ out)
{
    const int b = blockIdx.x;
    const int i = threadIdx.x;
    float m = g_pmax[((size_t)b * NJCHUNK + 0) * SQ + i];
#pragma unroll
    for (int jc = 1; jc < NJCHUNK; jc++)
        m = fmaxf(m, g_pmax[((size_t)b * NJCHUNK + jc) * SQ + i]);
#pragma unroll
    for (int o = 16; o > 0; o >>= 1)
        m += __shfl_xor_sync(0xffffffffu, m, o, 32);
    __shared__ float s[4];
    if ((i & 31) == 0) s[i >> 5] = m;
    __syncthreads();
    if (i == 0) out[b] = s[0] + s[1] + s[2] + s[3];
}

// ---------------------------------------------------------------------------
extern "C" void kernel_launch(void* const* d_in, const int* in_sizes, int n_in,
                              void* d_out, int out_size)
{
    const float* qh = (const float*)d_in[0];   // [64,128,768]
    const int*   qm = (const int*)  d_in[1];   // [64,128]
    const float* dh = (const float*)d_in[2];   // [64,1024,768]
    const int*   dm = (const int*)  d_in[3];   // [64,1024]
    const float* W  = (const float*)d_in[4];   // [128,768]
    float* out = (float*)d_out;                // [64]

    cudaFuncSetAttribute(proj_tc,   cudaFuncAttributeMaxDynamicSharedMemorySize, PROJ_SMEM);
    cudaFuncSetAttribute(maxsim_tc, cudaFuncAttributeMaxDynamicSharedMemorySize, MS_SMEM);

    cvt_w<<<(DDIM * HDIM / 4) / 256, 256>>>(W);
    proj_tc<<<NBLK_Q + NBLK_D, 320, PROJ_SMEM>>>(qh, qm, dh, dm);
    maxsim_tc<<<dim3(BATCH, NJCHUNK), 256, MS_SMEM>>>();
    finalize_kernel<<<BATCH, 128>>>(out);
}

// round 16
// speedup vs baseline: 1.9918x; 1.0204x over previous
#include <cuda_runtime.h>
#include <cuda_fp16.h>
#include <math.h>
#include <stdint.h>

// Problem constants
#define HDIM 768
#define DDIM 128
#define BATCH 64
#define SQ 128
#define SD 1024
#define NTOK_Q (BATCH * SQ)   // 8192
#define NTOK_D (BATCH * SD)   // 65536
#define NJCHUNK 8             // SD / 128
#define NBLK_Q (NTOK_Q / 128) // 64
#define NBLK_D (NTOK_D / 128) // 512

#define KC 32                 // K chunk (elements)
#define NSTAGE 3
#define LDH 40                // fp16 stage row stride (units): 80B = 5x16B odd
#define HSTG (128 * LDH * 2)  // 10240 B per fp16 stage
#define RAWLD 36              // raw fp32 row stride (floats): 144B = 9x16B odd
#define RAWSTG (128 * RAWLD * 4)   // 18432 B
#define RING_OFF 1024

// proj layout (relative to ring = smem + RING_OFF):
//   raw X ring 3*RAWSTG @0, W fp16 ring 3*HSTG @55296, Abuf 2*HSTG @86016, RED @106496
#define PBRING_OFF (3 * RAWSTG)            // 55296
#define ABUF_OFF  (PBRING_OFF + 3 * HSTG)  // 86016
#define PROJ_RED  (ABUF_OFF + 2 * HSTG)    // 106496
#define PROJ_SMEM (RING_OFF + PROJ_RED + 2048)   // 109568

// maxsim layout: A 3 stages @0, B 3 stages @3*HSTG, RED @6*HSTG
#define MS_BOFF  (3 * HSTG)
#define MS_RED   (6 * HSTG)
#define MS_SMEM  (RING_OFF + MS_RED + 2048)      // 64512

// Scratch (device globals: allocation-free per harness rules)
__device__ __half g_q_emb[NTOK_Q * DDIM];            // 2 MB
__device__ __half g_d_emb[(size_t)NTOK_D * DDIM];    // 16 MB
__device__ float  g_pmax[BATCH * NJCHUNK * SQ];      // 256 KB
__device__ __half g_w_h[DDIM * HDIM];                // 192 KB (fp16 W)

// ---------------------------------------------------------------------------
// helpers
// ---------------------------------------------------------------------------
__device__ __forceinline__ uint32_t s2u(const void* p) {
    return (uint32_t)__cvta_generic_to_shared(p);
}
__device__ __forceinline__ void cp16(uint32_t smem, const void* g) {
    asm volatile("cp.async.cg.shared.global [%0], [%1], 16;" :: "r"(smem), "l"(g));
}
#define CP_COMMIT() asm volatile("cp.async.commit_group;" ::: "memory")
#define CP_WAIT(n)  asm volatile("cp.async.wait_group %0;" :: "n"(n) : "memory")

#define MBARRIER_INIT(mb, n) \
    asm volatile("mbarrier.init.shared.b64 [%0], %1;" :: "r"((uint32_t)(mb)), "r"((uint32_t)(n)) : "memory")
#define MBARRIER_ARRIVE(mb) \
    asm volatile("mbarrier.arrive.shared.b64 _, [%0];" :: "r"((uint32_t)(mb)) : "memory")

__device__ __forceinline__ void mbar_wait(uint32_t mb, uint32_t parity) {
    uint32_t done;
    asm volatile("{\n\t.reg .pred p;\n\t"
                 "mbarrier.try_wait.parity.acquire.cta.shared::cta.b64 p, [%1], %2;\n\t"
                 "selp.b32 %0, 1, 0, p;\n\t}" : "=r"(done) : "r"(mb), "r"(parity) : "memory");
    while (!done) {
        asm volatile("{\n\t.reg .pred p;\n\t"
                     "mbarrier.try_wait.parity.acquire.cta.shared::cta.b64 p, [%1], %2, 0x989680;\n\t"
                     "selp.b32 %0, 1, 0, p;\n\t}" : "=r"(done) : "r"(mb), "r"(parity) : "memory");
    }
}

__device__ __forceinline__ void ldsm4(uint32_t& r0, uint32_t& r1, uint32_t& r2,
                                      uint32_t& r3, uint32_t addr) {
    asm volatile("ldmatrix.sync.aligned.m8n8.x4.shared.b16 {%0,%1,%2,%3}, [%4];"
                 : "=r"(r0), "=r"(r1), "=r"(r2), "=r"(r3) : "r"(addr));
}
__device__ __forceinline__ void mma16(float c[4], const uint32_t a[4], const uint32_t b[2]) {
    asm volatile("mma.sync.aligned.m16n8k16.row.col.f32.f16.f16.f32 "
                 "{%0,%1,%2,%3}, {%4,%5,%6,%7}, {%8,%9}, {%0,%1,%2,%3};"
                 : "+f"(c[0]), "+f"(c[1]), "+f"(c[2]), "+f"(c[3])
                 : "r"(a[0]), "r"(a[1]), "r"(a[2]), "r"(a[3]),
                   "r"(b[0]), "r"(b[1]));
}

// barriers: full[s] @ sb+8+s*16, rawempty[s] @ +8, wempty[s] @ sb+56+s*16
#define MB_FULL(sb, s)  ((sb) + 8 + (uint32_t)(s) * 16)
#define MB_RAWE(sb, s)  ((sb) + 8 + (uint32_t)(s) * 16 + 8)
#define MB_WE(sb, s)    ((sb) + 56 + (uint32_t)(s) * 16)

// fp16 fragment offsets (units of __half), [rows][k] storage, stride LDH.
__device__ __forceinline__ void frag_offsets16(int warp, int lane,
                                               uint32_t aOff[2], uint32_t bOff[4],
                                               int& warpM, int& warpN)
{
    warpM = (warp & 3) * 32;
    warpN = (warp >> 2) * 64;
    const int l7 = lane & 7, b3 = (lane >> 3) & 1, b4 = (lane >> 4) & 1;
#pragma unroll
    for (int i = 0; i < 2; i++)
        aOff[i] = (uint32_t)((warpM + i * 16 + l7 + b3 * 8) * LDH + b4 * 8);
#pragma unroll
    for (int jj = 0; jj < 4; jj++)
        bOff[jj] = (uint32_t)((warpN + jj * 16 + b4 * 8 + l7) * LDH + b3 * 8);
}

// Consume one KC=32 fp16 stage: 2 k16 steps, each 6 ldsm.x4 + 16 mma per warp.
__device__ __forceinline__ void consume_stage16(uint32_t aB, uint32_t bB,
                                                const uint32_t aOff[2],
                                                const uint32_t bOff[4],
                                                float acc[2][8][4])
{
#pragma unroll
    for (int ks = 0; ks < 2; ks++) {
        const uint32_t kb = ks * 32;   // 16 fp16 = 32 bytes
        uint32_t af[2][4], bf[8][2];
#pragma unroll
        for (int i = 0; i < 2; i++)
            ldsm4(af[i][0], af[i][1], af[i][2], af[i][3], aB + aOff[i] * 2 + kb);
#pragma unroll
        for (int jj = 0; jj < 4; jj++) {
            uint32_t r0, r1, r2, r3;
            ldsm4(r0, r1, r2, r3, bB + bOff[jj] * 2 + kb);
            bf[2 * jj][0] = r0;  bf[2 * jj][1] = r1;
            bf[2 * jj + 1][0] = r2;  bf[2 * jj + 1][1] = r3;
        }
#pragma unroll
        for (int i = 0; i < 2; i++)
#pragma unroll
            for (int j = 0; j < 8; j++) mma16(acc[i][j], af[i], bf[j]);
    }
}

// ---------------------------------------------------------------------------
// Kernel 0: convert W fp32 -> fp16 once (cp.async-able stream for producers).
// ---------------------------------------------------------------------------
__global__ __launch_bounds__(256) void cvt_w(const float* __restrict__ W)
{
    int i = blockIdx.x * 256 + threadIdx.x;      // float4 index
    float4 v = ((const float4*)W)[i];
    __half2 h0 = __floats2half2_rn(v.x, v.y);
    __half2 h1 = __floats2half2_rn(v.z, v.w);
    uint2 u;
    u.x = *(uint32_t*)&h0;  u.y = *(uint32_t*)&h1;
    *(uint2*)&g_w_h[(size_t)i * 4] = u;
}

// ---------------------------------------------------------------------------
// Kernel 1: projection + L2 normalize, fp16, warp-specialized.
// R15 structure + PAIR-LOCAL cvt sync: warp w converts float-cols
// [(w>>2)*16, +16) of its OWN A rows [warpM, warpM+32); only warps w and w+4
// touch those Abuf rows, so a 64-thread named barrier (id 2+(w&3)) replaces
// the block-wide bar.sync -> the four warp pairs pipeline independently.
// ---------------------------------------------------------------------------
__global__ __launch_bounds__(320, 2) void proj_tc(
    const float* __restrict__ Xq, const int* __restrict__ Mq,
    const float* __restrict__ Xd, const int* __restrict__ Md)
{
    extern __shared__ char smem[];
    const uint32_t sbase = s2u(smem);
    const uint32_t ring  = sbase + RING_OFF;
    const int tid  = threadIdx.x;
    const int lane = tid & 31;
    const int warp = tid >> 5;

    const bool isQ = blockIdx.x < NBLK_Q;
    const int  rb  = isQ ? blockIdx.x : (blockIdx.x - NBLK_Q);
    const int  row0 = rb * 128;
    const float* X = isQ ? Xq : Xd;
    const int*   M = isQ ? Mq : Md;
    __half*      E = isQ ? g_q_emb : g_d_emb;
    const float* gA = X + (size_t)row0 * HDIM;

    if (tid == 0) {
#pragma unroll
        for (int s = 0; s < NSTAGE; s++) {
            MBARRIER_INIT(MB_FULL(sbase, s), 64);
            MBARRIER_INIT(MB_RAWE(sbase, s), 256);
            MBARRIER_INIT(MB_WE(sbase, s), 256);
        }
    }
    __syncthreads();
    const int NC = HDIM / KC;   // 24

    if (warp >= 8) {
        // ------------- PRODUCER (warps 8,9): cp.async only -------------
        const int ptid = tid - 256;
        int ph = 1;
        for (int m = 0; m < NC; m++) {
            const int st = m % NSTAGE;
            mbar_wait(MB_RAWE(sbase, st), (uint32_t)ph);
            const float* a = gA + m * KC;
            const uint32_t rawdst = ring + (uint32_t)st * RAWSTG;
#pragma unroll
            for (int i = 0; i < 16; i++) {
                int idx = ptid + i * 64;
                int r = idx >> 3, c = (idx & 7) * 4;
                cp16(rawdst + (uint32_t)(r * RAWLD + c) * 4, a + (size_t)r * HDIM + c);
            }
            mbar_wait(MB_WE(sbase, st), (uint32_t)ph);
            const __half* w = g_w_h + m * KC;
            const uint32_t bdst = ring + PBRING_OFF + (uint32_t)st * HSTG;
#pragma unroll
            for (int i = 0; i < 8; i++) {
                int idx = ptid + i * 64;
                int r = idx >> 2, c8 = (idx & 3) * 8;
                cp16(bdst + (uint32_t)(r * LDH + c8) * 2, w + (size_t)r * HDIM + c8);
            }
            CP_COMMIT();
            if (m >= 2) { CP_WAIT(2); MBARRIER_ARRIVE(MB_FULL(sbase, (m - 2) % NSTAGE)); }
            if (st == NSTAGE - 1) ph ^= 1;
        }
        CP_WAIT(1); MBARRIER_ARRIVE(MB_FULL(sbase, (NC - 2) % NSTAGE));
        CP_WAIT(0); MBARRIER_ARRIVE(MB_FULL(sbase, (NC - 1) % NSTAGE));
        return;
    }

    // ------------- CONSUMER (warps 0-7; 256 threads) -------------
    uint32_t aOff[2], bOff[4];
    int warpM, warpN;
    frag_offsets16(warp, lane, aOff, bOff, warpM, warpN);
    const int wn = warp >> 2;
    const int g = lane >> 2, tig = lane & 3;

    // pair-local cvt mapping: this thread converts float-cols [half*16, +16)
    // of row warpM + lane.  (warp w and w+4 cover the same rows, disjoint cols)
    const int cvt_row  = warpM + lane;
    const int cvt_half = wn;                 // 0 or 1
    const int pairbar  = 2 + (warp & 3);     // named barrier id per pair

    float acc[2][8][4];
#pragma unroll
    for (int i = 0; i < 2; i++)
#pragma unroll
        for (int j = 0; j < 8; j++)
#pragma unroll
            for (int e = 0; e < 4; e++) acc[i][j][e] = 0.f;

    {
        int st = 0, ph = 0;
        for (int k = 0; k < NC; k++) {
            mbar_wait(MB_FULL(sbase, st), (uint32_t)ph);
            // cvt: raw[st] fp32 -> Abuf[k&1] fp16 (own rows, own col half)
            const char* src = smem + RING_OFF + (size_t)st * RAWSTG
                            + cvt_row * (RAWLD * 4) + cvt_half * 64;
            char* dst = smem + RING_OFF + ABUF_OFF + (size_t)(k & 1) * HSTG
                      + cvt_row * (LDH * 2) + cvt_half * 32;
            float4 f0 = *(const float4*)(src);
            float4 f1 = *(const float4*)(src + 16);
            float4 f2 = *(const float4*)(src + 32);
            float4 f3 = *(const float4*)(src + 48);
            __half2 h0 = __floats2half2_rn(f0.x, f0.y);
            __half2 h1 = __floats2half2_rn(f0.z, f0.w);
            __half2 h2 = __floats2half2_rn(f1.x, f1.y);
            __half2 h3 = __floats2half2_rn(f1.z, f1.w);
            __half2 h4 = __floats2half2_rn(f2.x, f2.y);
            __half2 h5 = __floats2half2_rn(f2.z, f2.w);
            __half2 h6 = __floats2half2_rn(f3.x, f3.y);
            __half2 h7 = __floats2half2_rn(f3.z, f3.w);
            uint4 u0, u1;
            u0.x = *(uint32_t*)&h0;  u0.y = *(uint32_t*)&h1;
            u0.z = *(uint32_t*)&h2;  u0.w = *(uint32_t*)&h3;
            u1.x = *(uint32_t*)&h4;  u1.y = *(uint32_t*)&h5;
            u1.z = *(uint32_t*)&h6;  u1.w = *(uint32_t*)&h7;
            *(uint4*)(dst)      = u0;
            *(uint4*)(dst + 16) = u1;

            MBARRIER_ARRIVE(MB_RAWE(sbase, st));   // raw[st] reads done
            asm volatile("bar.sync %0, 64;" :: "r"(pairbar) : "memory");  // pair Abuf visible
            consume_stage16(ring + ABUF_OFF + (uint32_t)(k & 1) * HSTG,
                            ring + PBRING_OFF + (uint32_t)st * HSTG,
                            aOff, bOff, acc);
            MBARRIER_ARRIVE(MB_WE(sbase, st));     // W ring[st] reads done
            if (++st == NSTAGE) { st = 0; ph ^= 1; }
        }
    }
    asm volatile("bar.sync 1, 256;" ::: "memory");

    // ---- fused L2 normalize (mask folded into scale) ----
    float* ssb = (float*)(smem + RING_OFF + PROJ_RED);   // [2][128]
#pragma unroll
    for (int i = 0; i < 2; i++) {
        float sl = 0.f, sh = 0.f;
#pragma unroll
        for (int j = 0; j < 8; j++) {
            sl += acc[i][j][0] * acc[i][j][0] + acc[i][j][1] * acc[i][j][1];
            sh += acc[i][j][2] * acc[i][j][2] + acc[i][j][3] * acc[i][j][3];
        }
        sl += __shfl_xor_sync(0xffffffffu, sl, 1);
        sl += __shfl_xor_sync(0xffffffffu, sl, 2);
        sh += __shfl_xor_sync(0xffffffffu, sh, 1);
        sh += __shfl_xor_sync(0xffffffffu, sh, 2);
        if (tig == 0) {
            ssb[wn * 128 + warpM + i * 16 + g]     = sl;
            ssb[wn * 128 + warpM + i * 16 + 8 + g] = sh;
        }
    }
    asm volatile("bar.sync 1, 256;" ::: "memory");
#pragma unroll
    for (int i = 0; i < 2; i++) {
        const int rl = warpM + i * 16 + g;
        const int rh = rl + 8;
        const float scl = (float)M[row0 + rl] / fmaxf(sqrtf(ssb[rl] + ssb[128 + rl]), 1e-12f);
        const float sch = (float)M[row0 + rh] / fmaxf(sqrtf(ssb[rh] + ssb[128 + rh]), 1e-12f);
#pragma unroll
        for (int j = 0; j < 8; j++) {
            const int col = warpN + j * 8 + tig * 2;
            __half2 v;
            v = __floats2half2_rn(acc[i][j][0] * scl, acc[i][j][1] * scl);
            *(__half2*)&E[(size_t)(row0 + rl) * DDIM + col] = v;
            v = __floats2half2_rn(acc[i][j][2] * sch, acc[i][j][3] * sch);
            *(__half2*)&E[(size_t)(row0 + rh) * DDIM + col] = v;
        }
    }
}

// ---------------------------------------------------------------------------
// Kernel 2: per-batch similarity + partial max (fp16, 3-stage ring — R11).
// Block (b, jc): [128 q x 128 docs], K = 128 dims (4 chunks of 32).
// ---------------------------------------------------------------------------
__global__ __launch_bounds__(256, 2) void maxsim_tc()
{
    extern __shared__ char smem[];
    const uint32_t sbase = s2u(smem);
    const uint32_t ring  = sbase + RING_OFF;
    const int tid  = threadIdx.x;
    const int lane = tid & 31;
    const int warp = tid >> 5;
    const int b  = blockIdx.x;
    const int jc = blockIdx.y;

    const __half* q = g_q_emb + (size_t)b * SQ * DDIM;
    const __half* d = g_d_emb + ((size_t)b * SD + (size_t)jc * 128) * DDIM;

    uint32_t aOff[2], bOff[4];
    int warpM, warpN;
    frag_offsets16(warp, lane, aOff, bOff, warpM, warpN);
    const int wn = warp >> 2;
    const int g = lane >> 2, tig = lane & 3;

    float acc[2][8][4];
#pragma unroll
    for (int i = 0; i < 2; i++)
#pragma unroll
        for (int j = 0; j < 8; j++)
#pragma unroll
            for (int e = 0; e < 4; e++) acc[i][j][e] = 0.f;

    auto load_stage = [&](int st, int m) {
        const __half* a  = q + m * KC;
        const __half* dd = d + m * KC;
        const uint32_t smA = ring + (uint32_t)st * HSTG;
        const uint32_t smB = ring + MS_BOFF + (uint32_t)st * HSTG;
#pragma unroll
        for (int i = 0; i < 2; i++) {
            int idx = tid + i * 256;         // [0,512)
            int r = idx >> 2, c8 = (idx & 3) * 8;
            uint32_t off = (uint32_t)(r * LDH + c8) * 2;
            cp16(smA + off, a + (size_t)r * DDIM + c8);
            cp16(smB + off, dd + (size_t)r * DDIM + c8);
        }
    };

    load_stage(0, 0); CP_COMMIT();
    load_stage(1, 1); CP_COMMIT();

    const int NC = DDIM / KC;   // 4
    int st = 0, stn = 2;
    for (int k = 0; k < NC; k++) {
        CP_WAIT(1);
        __syncthreads();
        const int m = k + 2;
        if (m < NC) { load_stage(stn, m); CP_COMMIT(); }
        consume_stage16(ring + (uint32_t)st * HSTG,
                        ring + MS_BOFF + (uint32_t)st * HSTG,
                        aOff, bOff, acc);
        st = (st + 1 == NSTAGE) ? 0 : st + 1;
        stn = (stn + 1 == NSTAGE) ? 0 : stn + 1;
    }
    __syncthreads();

    // ---- row max over this 128-doc chunk ----
    float* mxb = (float*)(smem + RING_OFF + MS_RED);   // [2][128]
#pragma unroll
    for (int i = 0; i < 2; i++) {
        float ml = acc[i][0][0], mh = acc[i][0][2];
#pragma unroll
        for (int j = 0; j < 8; j++) {
            ml = fmaxf(ml, fmaxf(acc[i][j][0], acc[i][j][1]));
            mh = fmaxf(mh, fmaxf(acc[i][j][2], acc[i][j][3]));
        }
        ml = fmaxf(ml, __shfl_xor_sync(0xffffffffu, ml, 1));
        ml = fmaxf(ml, __shfl_xor_sync(0xffffffffu, ml, 2));
        mh = fmaxf(mh, __shfl_xor_sync(0xffffffffu, mh, 1));
        mh = fmaxf(mh, __shfl_xor_sync(0xffffffffu, mh, 2));
        if (tig == 0) {
            mxb[wn * 128 + warpM + i * 16 + g]     = ml;
            mxb[wn * 128 + warpM + i * 16 + 8 + g] = mh;
        }
    }
    __syncthreads();
    if (tid < 128)
        g_pmax[((size_t)b * NJCHUNK + jc) * SQ + tid] =
            fmaxf(mxb[tid], mxb[128 + tid]);
}

// ---------------------------------------------------------------------------
// Kernel 3: finalize. out[b] = sum_i max_jc pmax[b, jc, i]
// ---------------------------------------------------------------------------
__global__ __launch_bounds__(128) void finalize_kernel(float* __restrict__ out)
{
    const int b = blockIdx.x;
    const int i = threadIdx.x;
    float m = g_pmax[((size_t)b * NJCHUNK + 0) * SQ + i];
#pragma unroll
    for (int jc = 1; jc < NJCHUNK; jc++)
        m = fmaxf(m, g_pmax[((size_t)b * NJCHUNK + jc) * SQ + i]);
#pragma unroll
    for (int o = 16; o > 0; o >>= 1)
        m += __shfl_xor_sync(0xffffffffu, m, o, 32);
    __shared__ float s[4];
    if ((i & 31) == 0) s[i >> 5] = m;
    __syncthreads();
    if (i == 0) out[b] = s[0] + s[1] + s[2] + s[3];
}

// ---------------------------------------------------------------------------
extern "C" void kernel_launch(void* const* d_in, const int* in_sizes, int n_in,
                              void* d_out, int out_size)
{
    const float* qh = (const float*)d_in[0];   // [64,128,768]
    const int*   qm = (const int*)  d_in[1];   // [64,128]
    const float* dh = (const float*)d_in[2];   // [64,1024,768]
    const int*   dm = (const int*)  d_in[3];   // [64,1024]
    const float* W  = (const float*)d_in[4];   // [128,768]
    float* out = (float*)d_out;                // [64]

    cudaFuncSetAttribute(proj_tc,   cudaFuncAttributeMaxDynamicSharedMemorySize, PROJ_SMEM);
    cudaFuncSetAttribute(maxsim_tc, cudaFuncAttributeMaxDynamicSharedMemorySize, MS_SMEM);

    cvt_w<<<(DDIM * HDIM / 4) / 256, 256>>>(W);
    proj_tc<<<NBLK_Q + NBLK_D, 320, PROJ_SMEM>>>(qh, qm, dh, dm);
    maxsim_tc<<<dim3(BATCH, NJCHUNK), 256, MS_SMEM>>>();
    finalize_kernel<<<BATCH, 128>>>(out);
}